// round 16
// baseline (speedup 1.0000x reference)
#include <cuda_runtime.h>
#include <cstdint>

#define Bdim 4
#define Hdim 32
#define Tdim 2048
#define Kdim 64
#define Vdim 64
#define CHUNK 32
#define NCHUNK (Tdim / CHUNK)
#define NTHREADS 512
#define CHUNK_BYTES (CHUNK * Kdim * 4)   // 8192 B per tensor per chunk

// ---- packed f32x2 helpers (sm_103a FFMA2 path) ----
__device__ __forceinline__ float2 fma2(float2 a, float2 b, float2 c) {
    float2 d;
    asm("fma.rn.f32x2 %0, %1, %2, %3;"
        : "=l"(reinterpret_cast<unsigned long long&>(d))
        : "l"(reinterpret_cast<unsigned long long&>(a)),
          "l"(reinterpret_cast<unsigned long long&>(b)),
          "l"(reinterpret_cast<unsigned long long&>(c)));
    return d;
}
__device__ __forceinline__ float2 mul2(float2 a, float2 b) {
    float2 d;
    asm("mul.rn.f32x2 %0, %1, %2;"
        : "=l"(reinterpret_cast<unsigned long long&>(d))
        : "l"(reinterpret_cast<unsigned long long&>(a)),
          "l"(reinterpret_cast<unsigned long long&>(b)));
    return d;
}

__device__ __forceinline__ void cp16(uint32_t smem_dst, const void* gmem_src) {
    asm volatile("cp.async.cg.shared.global [%0], [%1], 16;"
                 :: "r"(smem_dst), "l"(gmem_src));
}

// Block = one (b,h). 512 threads: ks = tid&15 (K split 16x4), vg = tid>>4 (V split 32x2).
// Each thread owns a 4k x 2v state tile in registers (4 packed float2).
// Per step: o_v = sum_k q_k*S_kv + v_v*(sum_k q_k*u_k*k_k);  S = S*exp(w) + k*v.
// Per step: one xor8 shfl distributes the 2 v-partials over the b3 halves;
// the remaining sum over 8 reduce-lanes is batched over 8 steps via a 3-stage
// value-distribution butterfly (7 shfls / 8 steps); lane ks&7 stores step tb+(ks&7).
// The squk*v bias is injected once into P[] at lane ks&7==0.
__global__ __launch_bounds__(NTHREADS, 1)
void rwkv6_scan_kernel(const float* __restrict__ r,
                       const float* __restrict__ kin,
                       const float* __restrict__ vin,
                       const float* __restrict__ win,
                       const float* __restrict__ uin,
                       const float* __restrict__ h0,
                       float* __restrict__ o,
                       float* __restrict__ hT) {
    const int bh    = blockIdx.x;
    const int h     = bh % Hdim;
    const int tid   = threadIdx.x;
    const int ks    = tid & 15;
    const int vg    = tid >> 4;          // 0..31 (2 per warp)
    const int kbase = ks * 4;
    const int vbase = vg * 2;
    const bool b3   = (ks & 8) != 0;
    const bool b2   = (ks & 4) != 0;
    const bool c1   = (ks & 2) != 0;
    const bool c0   = (ks & 1) != 0;
    const bool bias_lane = (ks & 7) == 0;
    const int vidx  = vbase + (b3 ? 1 : 0);   // v owned by this lane after xor8

    __shared__ float sq[2][CHUNK][Kdim];   // 16 KB
    __shared__ float sk[2][CHUNK][Kdim];   // 16 KB
    __shared__ float sw[2][CHUNK][Kdim];   // 16 KB (exp applied in place)
    __shared__ float sv[2][CHUNK][Vdim];   // 16 KB
    __shared__ float squk[2][CHUNK];       // per-step  sum_k q*u*k
    __shared__ float su[Kdim];

    // state tile: s[v*2+p] holds S[kbase+2p .. kbase+2p+1][vbase+v]
    float2 s[4];
    {
        const size_t hb = (size_t)bh * Kdim * Vdim;
#pragma unroll
        for (int v = 0; v < 2; v++)
#pragma unroll
            for (int p = 0; p < 2; p++) {
                s[v * 2 + p].x = h0[hb + (size_t)(kbase + 2 * p)     * Vdim + vbase + v];
                s[v * 2 + p].y = h0[hb + (size_t)(kbase + 2 * p + 1) * Vdim + vbase + v];
            }
    }
    if (tid < Kdim) su[tid] = uin[h * Kdim + tid];

    const size_t base = (size_t)bh * Tdim * Kdim;   // also valid for v and o (K==V)

    const uint32_t sq_s = (uint32_t)__cvta_generic_to_shared(&sq[0][0][0]);
    const uint32_t sk_s = (uint32_t)__cvta_generic_to_shared(&sk[0][0][0]);
    const uint32_t sw_s = (uint32_t)__cvta_generic_to_shared(&sw[0][0][0]);
    const uint32_t sv_s = (uint32_t)__cvta_generic_to_shared(&sv[0][0][0]);

    // issue a chunk's 4 tensors as one cp.async group into buffer `buf`
    // 8192 B per tensor = 512 threads x 1 cp16 each
    auto issue_chunk = [&](int c, int buf) {
        const size_t off = base + (size_t)c * CHUNK * Kdim;
        const uint32_t so = buf * CHUNK_BYTES + tid * 16;
        const size_t go = off + tid * 4;
        cp16(sq_s + so, r   + go);
        cp16(sk_s + so, kin + go);
        cp16(sw_s + so, win + go);
        cp16(sv_s + so, vin + go);
        asm volatile("cp.async.commit_group;");
    };

    issue_chunk(0, 0);
    issue_chunk(1, 1);

#pragma unroll 1
    for (int c = 0; c < NCHUNK; c++) {
        const int cur = c & 1;
        asm volatile("cp.async.wait_group 1;");
        __syncthreads();

        // ---- per-chunk preprocessing ----
        // exp(w) in place: 2048 values / 512 threads = one float4 each
        {
            float4* wf = (float4*)&sw[cur][0][0];
            float4 t = wf[tid];
            t.x = __expf(t.x); t.y = __expf(t.y);
            t.z = __expf(t.z); t.w = __expf(t.w);
            wf[tid] = t;
        }
        // quk[t] = sum_k q*u*k : 32 steps x 16 lanes, 4 k's each
        {
            const int stp  = tid >> 4;           // 0..31
            const int part = tid & 15;           // 0..15
            const float4 q4 = *(const float4*)&sq[cur][stp][part * 4];
            const float4 k4 = *(const float4*)&sk[cur][stp][part * 4];
            const float4 u4 = *(const float4*)&su[part * 4];
            float sum = q4.x * k4.x * u4.x;
            sum = fmaf(q4.y * k4.y, u4.y, sum);
            sum = fmaf(q4.z * k4.z, u4.z, sum);
            sum = fmaf(q4.w * k4.w, u4.w, sum);
            sum += __shfl_xor_sync(0xffffffffu, sum, 1);
            sum += __shfl_xor_sync(0xffffffffu, sum, 2);
            sum += __shfl_xor_sync(0xffffffffu, sum, 4);
            sum += __shfl_xor_sync(0xffffffffu, sum, 8);
            if (part == 0) squk[cur][stp] = sum;
        }
        __syncthreads();

        // ---- compute CHUNK steps in batches of 8, no barriers ----
        const size_t obase = base + (size_t)c * CHUNK * Vdim;
#pragma unroll 1
        for (int tb = 0; tb < CHUNK; tb += 8) {
            float P[8];   // per-step partials after xor8 (compile-time indexed)
#pragma unroll
            for (int t8 = 0; t8 < 8; t8++) {
                const int tt = tb + t8;
                const float4 q4 = *(const float4*)&sq[cur][tt][kbase];
                const float4 k4 = *(const float4*)&sk[cur][tt][kbase];
                const float4 e4 = *(const float4*)&sw[cur][tt][kbase];
                const float2 v2 = *(const float2*)&sv[cur][tt][vbase];
                const float squk_t = squk[cur][tt];

                const float2 q2a = make_float2(q4.x, q4.y);
                const float2 q2b = make_float2(q4.z, q4.w);
                const float2 k2a = make_float2(k4.x, k4.y);
                const float2 k2b = make_float2(k4.z, k4.w);
                const float2 e2a = make_float2(e4.x, e4.y);
                const float2 e2b = make_float2(e4.z, e4.w);

                float a0, a1;
                {
                    const float2 vv = make_float2(v2.x, v2.x);
                    const float2 kva = mul2(k2a, vv);
                    const float2 kvb = mul2(k2b, vv);
                    float2 acc = mul2(q2a, s[0]);
                    acc = fma2(q2b, s[1], acc);
                    s[0] = fma2(s[0], e2a, kva);
                    s[1] = fma2(s[1], e2b, kvb);
                    a0 = acc.x + acc.y;
                }
                {
                    const float2 vv = make_float2(v2.y, v2.y);
                    const float2 kva = mul2(k2a, vv);
                    const float2 kvb = mul2(k2b, vv);
                    float2 acc = mul2(q2a, s[2]);
                    acc = fma2(q2b, s[3], acc);
                    s[2] = fma2(s[2], e2a, kva);
                    s[3] = fma2(s[3], e2b, kvb);
                    a1 = acc.x + acc.y;
                }

                // xor8: distribute v0 to b3=0 lanes, v1 to b3=1 lanes
                const float send = b3 ? a0 : a1;
                const float recv = __shfl_xor_sync(0xffffffffu, send, 8);
                float p = (b3 ? a1 : a0) + recv;
                // inject bias squk*v exactly once (lane ks&7==0 of each group)
                if (bias_lane)
                    p = fmaf(squk_t, b3 ? v2.y : v2.x, p);
                P[t8] = p;
            }

            // batched tail: sum over the 8 reduce-lanes while distributing the
            // 8 steps, so lane ks ends with full o for (t = tb + (ks&7), vidx).
            // stage xor4 (4 sends)
            const float s40 = b2 ? P[0] : P[4];
            const float s41 = b2 ? P[1] : P[5];
            const float s42 = b2 ? P[2] : P[6];
            const float s43 = b2 ? P[3] : P[7];
            const float q0 = (b2 ? P[4] : P[0]) + __shfl_xor_sync(0xffffffffu, s40, 4);
            const float q1 = (b2 ? P[5] : P[1]) + __shfl_xor_sync(0xffffffffu, s41, 4);
            const float q2 = (b2 ? P[6] : P[2]) + __shfl_xor_sync(0xffffffffu, s42, 4);
            const float q3 = (b2 ? P[7] : P[3]) + __shfl_xor_sync(0xffffffffu, s43, 4);
            // stage xor2 (2 sends)
            const float s20 = c1 ? q0 : q2;
            const float s21 = c1 ? q1 : q3;
            const float r0 = (c1 ? q2 : q0) + __shfl_xor_sync(0xffffffffu, s20, 2);
            const float r1 = (c1 ? q3 : q1) + __shfl_xor_sync(0xffffffffu, s21, 2);
            // stage xor1 (1 send)
            const float s10 = c0 ? r0 : r1;
            const float red = (c0 ? r1 : r0) + __shfl_xor_sync(0xffffffffu, s10, 1);

            const int tsel = tb + (ks & 7);
            o[obase + (size_t)tsel * Vdim + vidx] = red;
        }

        __syncthreads();   // all reads of `cur` done before refill

        if (c + 2 < NCHUNK)
            issue_chunk(c + 2, cur);
    }

    // final state: layout (B,H,K,V)
    {
        const size_t hb = (size_t)bh * Kdim * Vdim;
#pragma unroll
        for (int v = 0; v < 2; v++)
#pragma unroll
            for (int p = 0; p < 2; p++) {
                hT[hb + (size_t)(kbase + 2 * p)     * Vdim + vbase + v] = s[v * 2 + p].x;
                hT[hb + (size_t)(kbase + 2 * p + 1) * Vdim + vbase + v] = s[v * 2 + p].y;
            }
    }
}

extern "C" void kernel_launch(void* const* d_in, const int* in_sizes, int n_in,
                              void* d_out, int out_size) {
    const float* r  = (const float*)d_in[0];
    const float* k  = (const float*)d_in[1];
    const float* v  = (const float*)d_in[2];
    const float* w  = (const float*)d_in[3];
    const float* u  = (const float*)d_in[4];
    const float* h0 = (const float*)d_in[5];

    float* o  = (float*)d_out;
    float* hT = o + (size_t)Bdim * Hdim * Tdim * Vdim;

    rwkv6_scan_kernel<<<Bdim * Hdim, NTHREADS>>>(r, k, v, w, u, h0, o, hT);
}